// round 9
// baseline (speedup 1.0000x reference)
#include <cuda_runtime.h>
#include <math.h>

// Problem dims
#define S_LEN   512
#define BATCH   256
#define DIN     256
#define HID     512
#define HIST    2048
#define NB      128            // persistent CTAs (<= SM count, all co-resident)

// ---------------- device scratch (no allocs allowed) ----------------
__device__ float d_Wp[768 * 1536];            // packed weights, k-major (4.5 MB)
__device__ float d_h[2][BATCH * HID];         // ping-pong hidden state
__device__ float d_g[BATCH * HIST];           // alpha logits
__device__ float d_alpha[BATCH * HIST];
__device__ float d_sig[BATCH * DIN];
__device__ float d_mu[BATCH * DIN];
__device__ float d_inv_sigma[BATCH * DIN];
__device__ float d_logdet[BATCH];

// grid barrier state
__device__ unsigned int g_arrive;
__device__ volatile unsigned int g_release;

__global__ void reset_barrier_kernel() {
    g_arrive = 0;
    g_release = 0;
}

// ---------------- weight packing ----------------
// Wp[k][j], k in [0,768), j in [0,1536):
//   Wp[k][j] = (k<256) ? w_ih[j][k] : w_hh[j][k-256]
// j in [0,512): r-gate rows; [512,1024): z-gate rows; [1024,1536): n-gate rows
// (for n: k<256 contributes i_n, k>=256 contributes h_n — accumulated separately).
__global__ void pack_w_kernel(const float* __restrict__ w_ih,
                              const float* __restrict__ w_hh) {
    int idx = blockIdx.x * 256 + threadIdx.x;      // 768*1536 total
    int k = idx / 1536;
    int j = idx - k * 1536;
    float v = (k < 256) ? w_ih[j * 256 + k] : w_hh[j * 512 + (k - 256)];
    d_Wp[idx] = v;
}

__global__ void init_h_kernel(const float* __restrict__ hidden) {
    int i = blockIdx.x * 256 + threadIdx.x;        // 131072
    d_h[0][i] = hidden[i];
}

// ---------------- persistent fused GRU ----------------

__device__ __forceinline__ void grid_barrier(unsigned int gen) {
    __syncthreads();
    if (threadIdx.x == 0) {
        __threadfence();
        unsigned int prev = atomicAdd(&g_arrive, 1u);
        if (prev == NB - 1) {
            g_arrive = 0;              // all arrived; safe to reset
            __threadfence();
            g_release = gen;
        } else {
            while (g_release < gen) { }
            __threadfence();
        }
    }
    __syncthreads();
}

__device__ __forceinline__ void load_a(float (&ra)[8], const float* __restrict__ base,
                                       int ld, int row0, int koff, int tid) {
#pragma unroll
    for (int i = 0; i < 8; i++) {
        int idx = tid + (i << 7);
        int k = idx & 31, r = idx >> 5;
        ra[i] = base[(row0 + r) * ld + koff + k];
    }
}

__device__ __forceinline__ void load_b(float (&rb)[24], int kk0, int col0, int tid) {
#pragma unroll
    for (int p = 0; p < 3; p++)
#pragma unroll
        for (int i = 0; i < 8; i++) {
            int idx = tid + (i << 7);
            int c = idx & 31, k = idx >> 5;
            rb[p * 8 + i] = d_Wp[(size_t)(kk0 + k) * 1536 + (p << 9) + col0 + c];
        }
}

__device__ __forceinline__ void store_smem(float (&sA)[32][36], float (&sB)[3][32][34],
                                           const float (&ra)[8], const float (&rb)[24],
                                           int tid) {
#pragma unroll
    for (int i = 0; i < 8; i++) {
        int idx = tid + (i << 7);
        int k = idx & 31, r = idx >> 5;
        sA[k][r] = ra[i];
    }
#pragma unroll
    for (int p = 0; p < 3; p++)
#pragma unroll
        for (int i = 0; i < 8; i++) {
            int idx = tid + (i << 7);
            int c = idx & 31, k = idx >> 5;
            sB[p][k][c] = rb[p * 8 + i];
        }
}

__device__ __forceinline__ void compute_chunk(const float (&sA)[32][36],
                                              const float (&sB)[3][32][34],
                                              int tr4, int tc2,
                                              float (&aR)[4][2], float (&aZ)[4][2],
                                              float (&aN)[4][2]) {
#pragma unroll 8
    for (int k = 0; k < 32; k++) {
        float4 a = *(const float4*)&sA[k][tr4];
        float2 br = *(const float2*)&sB[0][k][tc2];
        float2 bz = *(const float2*)&sB[1][k][tc2];
        float2 bn = *(const float2*)&sB[2][k][tc2];
        float av[4] = {a.x, a.y, a.z, a.w};
#pragma unroll
        for (int i = 0; i < 4; i++) {
            aR[i][0] += av[i] * br.x;  aR[i][1] += av[i] * br.y;
            aZ[i][0] += av[i] * bz.x;  aZ[i][1] += av[i] * bz.y;
            aN[i][0] += av[i] * bn.x;  aN[i][1] += av[i] * bn.y;
        }
    }
}

__global__ __launch_bounds__(128) void gru_persistent(const float* __restrict__ x) {
    const int bid = blockIdx.x;
    const int rt = bid >> 4, ct = bid & 15;       // 8 row tiles x 16 col tiles
    const int row0 = rt * 32, col0 = ct * 32;
    const int tid = threadIdx.x;
    const int tr4 = (tid >> 4) << 2;              // row offset within tile (0,4,...,28)
    const int tc2 = (tid & 15) << 1;              // col offset within tile (0,2,...,30)

    __shared__ __align__(16) float sA[2][32][36];
    __shared__ __align__(16) float sB[2][3][32][34];

    float ra[8], rb[24];

    for (int t = 0; t < S_LEN; ++t) {
        const int par = t & 1;
        const float* __restrict__ h_in = d_h[par];
        const float* __restrict__ x_t = x + (size_t)t * (BATCH * DIN);

        float aR[4][2], aZ[4][2], aI[4][2], aH[4][2];
#pragma unroll
        for (int i = 0; i < 4; i++)
#pragma unroll
            for (int j = 0; j < 2; j++) {
                aR[i][j] = 0.f; aZ[i][j] = 0.f; aI[i][j] = 0.f; aH[i][j] = 0.f;
            }

        // prefetch chunk 0
        load_a(ra, x_t, DIN, row0, 0, tid);
        load_b(rb, 0, col0, tid);

        // 24 chunks of K=32: chunks 0..7 use x (n-panel -> aI),
        //                    chunks 8..23 use h (n-panel -> aH)
        for (int cc = 0; cc < 24; cc++) {
            const int b = cc & 1;
            store_smem(sA[b], sB[b], ra, rb, tid);
            __syncthreads();
            if (cc < 23) {
                int nk = (cc + 1) * 32;
                if (nk < 256) load_a(ra, x_t, DIN, row0, nk, tid);
                else          load_a(ra, h_in, HID, row0, nk - 256, tid);
                load_b(rb, nk, col0, tid);
            }
            if (cc < 8) compute_chunk(sA[b], sB[b], tr4, tc2, aR, aZ, aI);
            else        compute_chunk(sA[b], sB[b], tr4, tc2, aR, aZ, aH);
        }

        // fused gate epilogue: h_new = (1-z)*n + z*h
        float* __restrict__ hout = d_h[par ^ 1];
#pragma unroll
        for (int i = 0; i < 4; i++) {
            int row = row0 + tr4 + i;
#pragma unroll
            for (int j = 0; j < 2; j++) {
                int col = col0 + tc2 + j;
                float r = 1.f / (1.f + expf(-aR[i][j]));
                float z = 1.f / (1.f + expf(-aZ[i][j]));
                float n = tanhf(aI[i][j] + r * aH[i][j]);
                float hp = h_in[row * HID + col];
                hout[row * HID + col] = (1.f - z) * n + z * hp;
            }
        }

        grid_barrier((unsigned)(t + 1));
    }
}

// ---------------- generic tiled GEMM: C[256][N] = A[256][K] * op(B) ----------------
template <int TRANSB>
__global__ __launch_bounds__(128) void gemm_tile_kernel(
        const float* __restrict__ A, int lda,
        const float* __restrict__ Bm, int ldb,
        float* __restrict__ C, int ldc, int K, int colTiles) {
    int bid = blockIdx.x;
    int rt = bid / colTiles, ct = bid % colTiles;
    int row0 = rt * 32, col0 = ct * 64;

    __shared__ __align__(16) float sA[16][36];
    __shared__ __align__(16) float sB[16][68];

    int tid = threadIdx.x;
    int tr = tid >> 4, tc = tid & 15;

    float acc[4][4];
#pragma unroll
    for (int i = 0; i < 4; i++)
#pragma unroll
        for (int j = 0; j < 4; j++) acc[i][j] = 0.f;

    for (int kk0 = 0; kk0 < K; kk0 += 16) {
#pragma unroll
        for (int it = 0; it < 4; it++) {
            int idx = tid + it * 128;
            int k = idx & 15, r = idx >> 4;
            sA[k][r] = A[(size_t)(row0 + r) * lda + kk0 + k];
        }
        if (TRANSB) {
#pragma unroll
            for (int it = 0; it < 8; it++) {
                int idx = tid + it * 128;
                int k = idx & 15, j = idx >> 4;
                sB[k][j] = Bm[(size_t)(col0 + j) * ldb + kk0 + k];
            }
        } else {
#pragma unroll
            for (int it = 0; it < 8; it++) {
                int idx = tid + it * 128;
                int j = idx & 63, k = idx >> 6;
                sB[k][j] = Bm[(size_t)(kk0 + k) * ldb + col0 + j];
            }
        }
        __syncthreads();
#pragma unroll
        for (int k = 0; k < 16; k++) {
            float4 av = *(const float4*)&sA[k][tr << 2];
            float4 bv = *(const float4*)&sB[k][tc << 2];
            float a[4] = {av.x, av.y, av.z, av.w};
            float b[4] = {bv.x, bv.y, bv.z, bv.w};
#pragma unroll
            for (int i = 0; i < 4; i++)
#pragma unroll
                for (int j = 0; j < 4; j++) acc[i][j] += a[i] * b[j];
        }
        __syncthreads();
    }

#pragma unroll
    for (int i = 0; i < 4; i++) {
        float4 v = make_float4(acc[i][0], acc[i][1], acc[i][2], acc[i][3]);
        *(float4*)&C[(size_t)(row0 + (tr << 2) + i) * ldc + col0 + (tc << 2)] = v;
    }
}

// ---------------- softmax over 2048 history (per batch row) ----------------
__global__ __launch_bounds__(256) void softmax_kernel() {
    int b = blockIdx.x;
    const float* L = d_g + (size_t)b * HIST;
    float* A = d_alpha + (size_t)b * HIST;
    __shared__ float red[256];
    int tid = threadIdx.x;

    float m = -1e30f;
    for (int j = tid; j < HIST; j += 256) m = fmaxf(m, L[j]);
    red[tid] = m; __syncthreads();
    for (int s = 128; s > 0; s >>= 1) {
        if (tid < s) red[tid] = fmaxf(red[tid], red[tid + s]);
        __syncthreads();
    }
    m = red[0]; __syncthreads();

    float sum = 0.f;
    for (int j = tid; j < HIST; j += 256) {
        float e = expf(L[j] - m);
        A[j] = e;
        sum += e;
    }
    red[tid] = sum; __syncthreads();
    for (int s = 128; s > 0; s >>= 1) {
        if (tid < s) red[tid] += red[tid + s];
        __syncthreads();
    }
    float inv = 1.f / red[0];
    for (int j = tid; j < HIST; j += 256) A[j] *= inv;
}

// ---------------- sigma: inv_sigma = exp(-logit), logdet = sum(logit) ----------------
__global__ __launch_bounds__(256) void sigma_kernel() {
    int b = blockIdx.x, d = threadIdx.x;
    float t = d_sig[(size_t)b * DIN + d];
    d_inv_sigma[(size_t)b * DIN + d] = expf(-t);
    __shared__ float red[256];
    red[d] = t; __syncthreads();
    for (int s = 128; s > 0; s >>= 1) {
        if (d < s) red[d] += red[d + s];
        __syncthreads();
    }
    if (d == 0) d_logdet[b] = red[0];
}

// ---------------- final log-prob: warp per (s,b) ----------------
__global__ __launch_bounds__(256) void logprob_kernel(
        const float* __restrict__ x, float* __restrict__ out) {
    int w = (blockIdx.x << 3) + (threadIdx.x >> 5);   // s*256 + b
    int lane = threadIdx.x & 31;
    int b = w & 255;
    const float4* xr = (const float4*)(x + ((size_t)w << 8));
    const float4* mu = (const float4*)(d_mu + ((size_t)b << 8));
    const float4* iv = (const float4*)(d_inv_sigma + ((size_t)b << 8));
    float acc = 0.f;
#pragma unroll
    for (int c = 0; c < 2; c++) {
        int idx = lane + (c << 5);
        float4 xv = xr[idx], mv = mu[idx], sv = iv[idx];
        float d0 = (xv.x - mv.x) * sv.x;
        float d1 = (xv.y - mv.y) * sv.y;
        float d2 = (xv.z - mv.z) * sv.z;
        float d3 = (xv.w - mv.w) * sv.w;
        acc += d0 * d0 + d1 * d1 + d2 * d2 + d3 * d3;
    }
#pragma unroll
    for (int o = 16; o; o >>= 1) acc += __shfl_xor_sync(0xffffffffu, acc, o);
    if (lane == 0) {
        const float log2pi = 1.8378770664093453f;
        out[w] = -0.5f * (acc + 256.0f * log2pi) - d_logdet[b];
    }
}

// ---------------- launch ----------------
extern "C" void kernel_launch(void* const* d_in, const int* in_sizes, int n_in,
                              void* d_out, int out_size) {
    const float* x        = (const float*)d_in[0];
    const float* hidden   = (const float*)d_in[1];
    const float* external = (const float*)d_in[2];
    const float* w_ih     = (const float*)d_in[3];
    const float* w_hh     = (const float*)d_in[4];
    const float* w_alpha  = (const float*)d_in[5];
    const float* w_sigma  = (const float*)d_in[6];
    float* out = (float*)d_out;

    float *pH0, *pG, *pSig, *pAlpha, *pMu;
    cudaGetSymbolAddress((void**)&pH0, d_h);        // d_h[0]
    cudaGetSymbolAddress((void**)&pG, d_g);
    cudaGetSymbolAddress((void**)&pSig, d_sig);
    cudaGetSymbolAddress((void**)&pAlpha, d_alpha);
    cudaGetSymbolAddress((void**)&pMu, d_mu);

    reset_barrier_kernel<<<1, 1>>>();
    pack_w_kernel<<<(768 * 1536) / 256, 256>>>(w_ih, w_hh);
    init_h_kernel<<<(BATCH * HID) / 256, 256>>>(hidden);

    // entire 512-step GRU in ONE kernel (final h lands in d_h[0])
    gru_persistent<<<NB, 128>>>(x);

    // alpha logits [256 x 2048] = h @ w_alpha^T   (K=512)
    gemm_tile_kernel<1><<<8 * 32, 128>>>(pH0, HID, w_alpha, HID, pG, HIST, HID, 32);
    softmax_kernel<<<BATCH, 256>>>();
    // sigma logits [256 x 256] = h @ w_sigma^T    (K=512)
    gemm_tile_kernel<1><<<8 * 4, 128>>>(pH0, HID, w_sigma, HID, pSig, DIN, HID, 4);
    sigma_kernel<<<BATCH, 256>>>();
    // mu [256 x 256] = alpha @ external           (K=2048)
    gemm_tile_kernel<0><<<8 * 4, 128>>>(pAlpha, HIST, external, DIN, pMu, DIN, HIST, 4);

    logprob_kernel<<<(S_LEN * BATCH) / 8, 256>>>(x, out);
}

// round 11
// speedup vs baseline: 1.8770x; 1.8770x over previous
#include <cuda_runtime.h>
#include <cuda_bf16.h>
#include <math.h>

#define S_LEN 512
#define BATCH 256
#define DIN   256
#define HID   512
#define HIST  2048
#define NB    128

// ---------------- device scratch (no allocs allowed) ----------------
// x images: [t][rt4][kc8][row64][kl32] bf16 hi/lo
__device__ unsigned short d_xbf_hi[(size_t)S_LEN*4*8*2048];   // 64MB
__device__ unsigned short d_xbf_lo[(size_t)S_LEN*4*8*2048];   // 64MB
// h images: [par2][rt4][kc16][row64][kl32]
__device__ unsigned short d_hbf_hi[2*4*16*2048];
__device__ unsigned short d_hbf_lo[2*4*16*2048];
// W images: [ct32][kc24][p3][term2][j16][kl32]
__device__ unsigned short d_wbf[32*24*3*2*512];
__device__ float d_h[2][BATCH*HID];
__device__ float d_g[BATCH*HIST];
__device__ float d_alpha[BATCH*HIST];
__device__ float d_sig[BATCH*DIN];
__device__ float d_mu[BATCH*DIN];
__device__ float d_inv_sigma[BATCH*DIN];
__device__ float d_logdet[BATCH];
__device__ unsigned int g_arrive;
__device__ volatile unsigned int g_release;

__global__ void reset_barrier_kernel() { g_arrive = 0; g_release = 0; }

// ---------------- PTX helpers (sm_80-compatible only) ----------------
__device__ __forceinline__ unsigned smem_u32(const void* p){
    unsigned a; asm("{ .reg .u64 t; cvta.to.shared.u64 t, %1; cvt.u32.u64 %0, t; }":"=r"(a):"l"(p)); return a;
}
__device__ __forceinline__ void ldsm4(unsigned* r, unsigned addr){
    asm volatile("ldmatrix.sync.aligned.m8n8.x4.shared.b16 {%0,%1,%2,%3}, [%4];"
        : "=r"(r[0]),"=r"(r[1]),"=r"(r[2]),"=r"(r[3]) : "r"(addr));
}
__device__ __forceinline__ void mma16816(float* c, const unsigned* a, unsigned b0, unsigned b1){
    asm volatile("mma.sync.aligned.m16n8k16.row.col.f32.bf16.bf16.f32 "
        "{%0,%1,%2,%3}, {%4,%5,%6,%7}, {%8,%9}, {%0,%1,%2,%3};"
        : "+f"(c[0]),"+f"(c[1]),"+f"(c[2]),"+f"(c[3])
        : "r"(a[0]),"r"(a[1]),"r"(a[2]),"r"(a[3]), "r"(b0),"r"(b1));
}
__device__ __forceinline__ void cpasync16(unsigned s, const void* g){
    asm volatile("cp.async.cg.shared.global [%0], [%1], 16;" :: "r"(s), "l"(g));
}
__device__ __forceinline__ void cpcommit(){ asm volatile("cp.async.commit_group;"); }
__device__ __forceinline__ void cpwait1(){ asm volatile("cp.async.wait_group 1;" ::: "memory"); }
__device__ __forceinline__ void cpwait0(){ asm volatile("cp.async.wait_group 0;" ::: "memory"); }
__device__ __forceinline__ float sigm(float x){ return 1.f/(1.f+expf(-x)); }

// ---------------- packing ----------------
__global__ __launch_bounds__(256) void pack_x_kernel(const float* __restrict__ x){
    unsigned idx = blockIdx.x*256u + threadIdx.x;    // 33,554,432
    int kl=idx&31, row=(idx>>5)&63, kc=(idx>>11)&7, rt=(idx>>14)&3, t=idx>>16;
    float v = x[((size_t)t*256 + rt*64 + row)*256 + kc*32 + kl];
    __nv_bfloat16 h = __float2bfloat16(v);
    __nv_bfloat16 l = __float2bfloat16(v - __bfloat162float(h));
    d_xbf_hi[idx] = *(unsigned short*)&h;
    d_xbf_lo[idx] = *(unsigned short*)&l;
}
__global__ __launch_bounds__(256) void pack_h0_kernel(const float* __restrict__ hidden){
    unsigned idx = blockIdx.x*256u + threadIdx.x;    // 131072
    int kl=idx&31, row=(idx>>5)&63, kc8=(idx>>11)&15, rt=idx>>15;
    float v = hidden[(size_t)(rt*64+row)*512 + kc8*32 + kl];
    __nv_bfloat16 h = __float2bfloat16(v);
    __nv_bfloat16 l = __float2bfloat16(v - __bfloat162float(h));
    size_t o = ((size_t)(0*4+rt)*16 + kc8)*2048 + row*32 + kl;
    d_hbf_hi[o] = *(unsigned short*)&h;
    d_hbf_lo[o] = *(unsigned short*)&l;
    d_h[0][(size_t)(rt*64+row)*512 + kc8*32 + kl] = v;
}
__global__ __launch_bounds__(256) void pack_w_kernel(const float* __restrict__ w_ih,
                                                     const float* __restrict__ w_hh){
    unsigned idx = blockIdx.x*256u + threadIdx.x;    // 1,179,648
    int kl = idx&31, j = (idx>>5)&15;
    int g = idx>>9;                  // 0..2303
    int p = g%3, kc = (g/3)%24, ct = g/72;
    int kg = kc*32 + kl;
    float w;
    if (p == 0){ int r = ct*16+j;        w = (kg<256)? w_ih[r*256+kg] : w_hh[r*512+kg-256]; }
    else if(p==1){ int r = 512+ct*16+j;  w = (kg<256)? w_ih[r*256+kg] : w_hh[r*512+kg-256]; }
    else { int r = 1024+ct*16+j;
           w = (kc<8)? w_ih[r*256+kg] : w_hh[r*512+kg-256]; }
    __nv_bfloat16 h = __float2bfloat16(w);
    __nv_bfloat16 l = __float2bfloat16(w - __bfloat162float(h));
    size_t base = (size_t)(ct*24+kc)*3072 + (p*2)*512 + j*32 + kl;
    d_wbf[base]       = *(unsigned short*)&h;
    d_wbf[base + 512] = *(unsigned short*)&l;
}

// ---------------- persistent HMMA GRU ----------------
__device__ __forceinline__ void grid_barrier(unsigned gen){
    __threadfence();
    __syncthreads();
    if(threadIdx.x==0){
        unsigned prev = atomicAdd(&g_arrive, 1u);
        if(prev == NB-1){ g_arrive = 0; __threadfence(); g_release = gen; }
        else { while(g_release < gen) {} __threadfence(); }
    }
    __syncthreads();
}

// smem tiles: row stride 40 shorts (80B) -> conflict-free ldmatrix phases
__device__ __forceinline__ void issue_chunk(int t,int par,int rt,int ct,int kc,int buf,
                                            unsigned sAb, unsigned sBb, int tid){
    const unsigned short* s0; const unsigned short* s1;
    if(kc<8){ size_t o=((size_t)(t*4+rt)*8+kc)*2048;        s0=d_xbf_hi+o; s1=d_xbf_lo+o; }
    else    { size_t o=((size_t)(par*4+rt)*16+(kc-8))*2048; s0=d_hbf_hi+o; s1=d_hbf_lo+o; }
#pragma unroll
    for(int i=0;i<4;i++){
        int id = tid + (i<<7);             // 0..511
        int term = id>>8, rest = id&255, row = rest>>2, q = rest&3;
        unsigned dst = sAb + 2u*((unsigned)((buf*2+term)*64+row)*40 + q*8);
        cpasync16(dst, (term? s1 : s0) + row*32 + q*8);
    }
    const unsigned short* ws = d_wbf + (size_t)(ct*24+kc)*3072;
#pragma unroll
    for(int i=0;i<3;i++){
        int id = tid + (i<<7);             // 0..383
        int p = id>>7, r2 = id&127, term = r2>>6, row = (r2>>2)&15, q = r2&3;
        unsigned dst = sBb + 2u*((unsigned)(((buf*3+p)*2+term)*16+row)*40 + q*8);
        cpasync16(dst, ws + (p*2+term)*512 + row*32 + q*8);
    }
}

__device__ __forceinline__ void compute_chunk(unsigned sAb, unsigned sBb, int buf, int w,
        unsigned laneoff, bool isIN,
        float* accR, float* accZ, float* accI, float* accH){
    unsigned aH = sAb + 2u*(unsigned)(((buf*2+0)*64 + w*16)*40) + laneoff;
    unsigned aL = sAb + 2u*(unsigned)(((buf*2+1)*64 + w*16)*40) + laneoff;
#pragma unroll
    for(int ks=0; ks<2; ks++){
        unsigned ko = (unsigned)(ks*32);   // +16 shorts
        unsigned ah[4], al[4];
        ldsm4(ah, aH + ko);
        ldsm4(al, aL + ko);
#pragma unroll
        for(int p=0;p<3;p++){
            unsigned bh[4], bl[4];
            unsigned bH = sBb + 2u*(unsigned)((((buf*3+p)*2+0)*16)*40) + laneoff + ko;
            unsigned bL = sBb + 2u*(unsigned)((((buf*3+p)*2+1)*16)*40) + laneoff + ko;
            ldsm4(bh, bH); ldsm4(bl, bL);
            float* acc = (p==0)? accR : (p==1)? accZ : (isIN? accI : accH);
            mma16816(acc,   ah, bh[0], bh[2]);
            mma16816(acc,   ah, bl[0], bl[2]);
            mma16816(acc,   al, bh[0], bh[2]);
            mma16816(acc+4, ah, bh[1], bh[3]);
            mma16816(acc+4, ah, bl[1], bl[3]);
            mma16816(acc+4, al, bh[1], bh[3]);
        }
    }
}

__global__ __launch_bounds__(128,1) void gru_hmma(){
    __shared__ __align__(16) unsigned short smA[2*2*64*40];
    __shared__ __align__(16) unsigned short smB[2*3*2*16*40];
    const int tid = threadIdx.x, lane = tid&31, w = tid>>5;
    const int bid = blockIdx.x, rt = bid>>5, ct = bid&31;
    unsigned sAb = smem_u32(smA), sBb = smem_u32(smB);
    const int sub = lane>>3;
    const unsigned laneoff = 2u*(unsigned)((((lane&7)+((sub&1)<<3))*40) + ((sub>>1)<<3));

    for(int t=0; t<S_LEN; ++t){
        const int par = t&1;
        float accR[8], accZ[8], accI[8], accH[8];
#pragma unroll
        for(int i=0;i<8;i++){ accR[i]=0.f; accZ[i]=0.f; accI[i]=0.f; accH[i]=0.f; }

        issue_chunk(t,par,rt,ct,0,0,sAb,sBb,tid); cpcommit();
        for(int kc=0; kc<24; ++kc){
            if(kc<23){ issue_chunk(t,par,rt,ct,kc+1,(kc+1)&1,sAb,sBb,tid); cpcommit(); cpwait1(); }
            else cpwait0();
            __syncthreads();
            compute_chunk(sAb,sBb,kc&1,w,laneoff,kc<8,accR,accZ,accI,accH);
            __syncthreads();
        }

        // ---- fused gate epilogue ----
        const float* hprevB = d_h[par];
        float* houtB = d_h[par^1];
        const int rbase = rt*64 + w*16 + (lane>>2);
        const int cb = ct*16 + 2*(lane&3);
        const int klb = (ct&1)*16 + 2*(lane&3);
        const size_t imgB = (((size_t)(par^1)*4 + rt)*16 + (ct>>1))*2048;
#pragma unroll
        for(int nb=0; nb<2; nb++)
#pragma unroll
        for(int rh=0; rh<2; rh++){
            int f = nb*4 + rh*2;
            int grow = rbase + rh*8;
            int gcol = cb + nb*8;
            float2 hp = *(const float2*)&hprevB[(size_t)grow*512 + gcol];
            float r0 = sigm(accR[f]),   r1 = sigm(accR[f+1]);
            float z0 = sigm(accZ[f]),   z1 = sigm(accZ[f+1]);
            float n0 = tanhf(accI[f]   + r0*accH[f]);
            float n1 = tanhf(accI[f+1] + r1*accH[f+1]);
            float h0 = (1.f-z0)*n0 + z0*hp.x;
            float h1 = (1.f-z1)*n1 + z1*hp.y;
            *(float2*)&houtB[(size_t)grow*512 + gcol] = make_float2(h0,h1);
            __nv_bfloat16 bh0=__float2bfloat16(h0), bh1=__float2bfloat16(h1);
            __nv_bfloat16 bl0=__float2bfloat16(h0-__bfloat162float(bh0));
            __nv_bfloat16 bl1=__float2bfloat16(h1-__bfloat162float(bh1));
            int rowl = w*16 + (lane>>2) + rh*8;
            size_t ii = imgB + (size_t)rowl*32 + klb + nb*8;
            *(unsigned*)&d_hbf_hi[ii] =
                (unsigned)*(unsigned short*)&bh0 | ((unsigned)*(unsigned short*)&bh1 << 16);
            *(unsigned*)&d_hbf_lo[ii] =
                (unsigned)*(unsigned short*)&bl0 | ((unsigned)*(unsigned short*)&bl1 << 16);
        }
        grid_barrier((unsigned)(t+1));
    }
}

// ---------------- tail: generic tiled GEMM ----------------
template <int TRANSB>
__global__ __launch_bounds__(128) void gemm_tile_kernel(
        const float* __restrict__ A, int lda, const float* __restrict__ Bm, int ldb,
        float* __restrict__ C, int ldc, int K, int colTiles){
    int bid=blockIdx.x, rt=bid/colTiles, ct=bid%colTiles;
    int row0=rt*32, col0=ct*64;
    __shared__ __align__(16) float sA[16][36];
    __shared__ __align__(16) float sB[16][68];
    int tid=threadIdx.x, tr=tid>>4, tc=tid&15;
    float acc[4][4];
#pragma unroll
    for(int i=0;i<4;i++)
#pragma unroll
        for(int j=0;j<4;j++) acc[i][j]=0.f;
    for(int kk0=0;kk0<K;kk0+=16){
#pragma unroll
        for(int it=0;it<4;it++){ int idx=tid+it*128; int k=idx&15, r=idx>>4;
            sA[k][r]=A[(size_t)(row0+r)*lda+kk0+k]; }
        if(TRANSB){
#pragma unroll
            for(int it=0;it<8;it++){ int idx=tid+it*128; int k=idx&15, j=idx>>4;
                sB[k][j]=Bm[(size_t)(col0+j)*ldb+kk0+k]; }
        } else {
#pragma unroll
            for(int it=0;it<8;it++){ int idx=tid+it*128; int j=idx&63, k=idx>>6;
                sB[k][j]=Bm[(size_t)(kk0+k)*ldb+col0+j]; }
        }
        __syncthreads();
#pragma unroll
        for(int k=0;k<16;k++){
            float4 av=*(const float4*)&sA[k][tr<<2];
            float4 bv=*(const float4*)&sB[k][tc<<2];
            float a[4]={av.x,av.y,av.z,av.w}, b[4]={bv.x,bv.y,bv.z,bv.w};
#pragma unroll
            for(int i=0;i<4;i++)
#pragma unroll
                for(int j=0;j<4;j++) acc[i][j]+=a[i]*b[j];
        }
        __syncthreads();
    }
#pragma unroll
    for(int i=0;i<4;i++){
        float4 v=make_float4(acc[i][0],acc[i][1],acc[i][2],acc[i][3]);
        *(float4*)&C[(size_t)(row0+(tr<<2)+i)*ldc+col0+(tc<<2)]=v;
    }
}

__global__ __launch_bounds__(256) void softmax_kernel(){
    int b=blockIdx.x;
    const float* L=d_g+(size_t)b*HIST; float* A=d_alpha+(size_t)b*HIST;
    __shared__ float red[256];
    int tid=threadIdx.x;
    float m=-1e30f;
    for(int j=tid;j<HIST;j+=256) m=fmaxf(m,L[j]);
    red[tid]=m; __syncthreads();
    for(int s=128;s>0;s>>=1){ if(tid<s) red[tid]=fmaxf(red[tid],red[tid+s]); __syncthreads(); }
    m=red[0]; __syncthreads();
    float sum=0.f;
    for(int j=tid;j<HIST;j+=256){ float e=expf(L[j]-m); A[j]=e; sum+=e; }
    red[tid]=sum; __syncthreads();
    for(int s=128;s>0;s>>=1){ if(tid<s) red[tid]+=red[tid+s]; __syncthreads(); }
    float inv=1.f/red[0];
    for(int j=tid;j<HIST;j+=256) A[j]*=inv;
}
__global__ __launch_bounds__(256) void sigma_kernel(){
    int b=blockIdx.x, d=threadIdx.x;
    float t=d_sig[(size_t)b*DIN+d];
    d_inv_sigma[(size_t)b*DIN+d]=expf(-t);
    __shared__ float red[256];
    red[d]=t; __syncthreads();
    for(int s=128;s>0;s>>=1){ if(d<s) red[d]+=red[d+s]; __syncthreads(); }
    if(d==0) d_logdet[b]=red[0];
}
__global__ __launch_bounds__(256) void logprob_kernel(
        const float* __restrict__ x, float* __restrict__ out){
    int w=(blockIdx.x<<3)+(threadIdx.x>>5);
    int lane=threadIdx.x&31, b=w&255;
    const float4* xr=(const float4*)(x+((size_t)w<<8));
    const float4* mu=(const float4*)(d_mu+((size_t)b<<8));
    const float4* iv=(const float4*)(d_inv_sigma+((size_t)b<<8));
    float acc=0.f;
#pragma unroll
    for(int c=0;c<2;c++){
        int idx=lane+(c<<5);
        float4 xv=xr[idx], mv=mu[idx], sv=iv[idx];
        float d0=(xv.x-mv.x)*sv.x, d1=(xv.y-mv.y)*sv.y;
        float d2=(xv.z-mv.z)*sv.z, d3=(xv.w-mv.w)*sv.w;
        acc+=d0*d0+d1*d1+d2*d2+d3*d3;
    }
#pragma unroll
    for(int o=16;o;o>>=1) acc+=__shfl_xor_sync(0xffffffffu,acc,o);
    if(lane==0){
        const float log2pi=1.8378770664093453f;
        out[w]=-0.5f*(acc+256.0f*log2pi)-d_logdet[b];
    }
}

// ---------------- launch ----------------
extern "C" void kernel_launch(void* const* d_in, const int* in_sizes, int n_in,
                              void* d_out, int out_size){
    const float* x        = (const float*)d_in[0];
    const float* hidden   = (const float*)d_in[1];
    const float* external = (const float*)d_in[2];
    const float* w_ih     = (const float*)d_in[3];
    const float* w_hh     = (const float*)d_in[4];
    const float* w_alpha  = (const float*)d_in[5];
    const float* w_sigma  = (const float*)d_in[6];
    float* out = (float*)d_out;

    float *pH0, *pG, *pSig, *pAlpha, *pMu;
    cudaGetSymbolAddress((void**)&pH0, d_h);
    cudaGetSymbolAddress((void**)&pG, d_g);
    cudaGetSymbolAddress((void**)&pSig, d_sig);
    cudaGetSymbolAddress((void**)&pAlpha, d_alpha);
    cudaGetSymbolAddress((void**)&pMu, d_mu);

    reset_barrier_kernel<<<1,1>>>();
    pack_x_kernel<<<131072,256>>>(x);
    pack_w_kernel<<<4608,256>>>(w_ih, w_hh);
    pack_h0_kernel<<<512,256>>>(hidden);

    gru_hmma<<<NB,128>>>();                 // final h lands in d_h[0]

    gemm_tile_kernel<1><<<8*32,128>>>(pH0, HID, w_alpha, HID, pG, HIST, HID, 32);
    softmax_kernel<<<BATCH,256>>>();
    gemm_tile_kernel<1><<<8*4,128>>>(pH0, HID, w_sigma, HID, pSig, DIN, HID, 4);
    sigma_kernel<<<BATCH,256>>>();
    gemm_tile_kernel<0><<<8*4,128>>>(pAlpha, HIST, external, DIN, pMu, DIN, HIST, 4);
    logprob_kernel<<<(S_LEN*BATCH)/8,256>>>(x, out);
}

// round 12
// speedup vs baseline: 3.5356x; 1.8837x over previous
#include <cuda_runtime.h>
#include <cuda_bf16.h>
#include <math.h>

#define S_LEN 512
#define BATCH 256
#define DIN   256
#define HID   512
#define HIST  2048
#define NB    128
#define SW_BYTES (144*1280)                 /* 184320: 24kc*3p*2term tiles of 16x40 shorts */
#define SA_STAGE 5120                       /* 64 rows x 40 shorts x 2B */
#define SMEM_DYN (SW_BYTES + 4*SA_STAGE)    /* 204800 */

// ---------------- device scratch ----------------
// x image: [t][rt4][kc8][row64][kl32] bf16 (hi only)
__device__ unsigned short d_xbf[(size_t)S_LEN*4*8*2048];     // 64MB
// h image: [par2][rt4][kc16][row64][kl32]
__device__ unsigned short d_hbf[2*4*16*2048];
// W image: [ct32][kc24][p3][term2][j16][kl32]  (hi+lo)
__device__ unsigned short d_wbf[32*24*3*2*512];
__device__ float d_h[2][BATCH*HID];
__device__ float d_g[BATCH*HIST];
__device__ float d_alpha[BATCH*HIST];
__device__ float d_sig[BATCH*DIN];
__device__ float d_mu[BATCH*DIN];
__device__ float d_inv_sigma[BATCH*DIN];
__device__ float d_logdet[BATCH];
__device__ unsigned int g_arrive;
__device__ volatile unsigned int g_release;

__global__ void reset_barrier_kernel() { g_arrive = 0; g_release = 0; }

// ---------------- PTX helpers ----------------
__device__ __forceinline__ unsigned smem_u32(const void* p){
    unsigned a; asm("{ .reg .u64 t; cvta.to.shared.u64 t, %1; cvt.u32.u64 %0, t; }":"=r"(a):"l"(p)); return a;
}
__device__ __forceinline__ void ldsm4(unsigned* r, unsigned addr){
    asm volatile("ldmatrix.sync.aligned.m8n8.x4.shared.b16 {%0,%1,%2,%3}, [%4];"
        : "=r"(r[0]),"=r"(r[1]),"=r"(r[2]),"=r"(r[3]) : "r"(addr));
}
__device__ __forceinline__ void mma16816(float* c, const unsigned* a, unsigned b0, unsigned b1){
    asm volatile("mma.sync.aligned.m16n8k16.row.col.f32.bf16.bf16.f32 "
        "{%0,%1,%2,%3}, {%4,%5,%6,%7}, {%8,%9}, {%0,%1,%2,%3};"
        : "+f"(c[0]),"+f"(c[1]),"+f"(c[2]),"+f"(c[3])
        : "r"(a[0]),"r"(a[1]),"r"(a[2]),"r"(a[3]), "r"(b0),"r"(b1));
}
__device__ __forceinline__ void cpasync16(unsigned s, const void* g){
    asm volatile("cp.async.cg.shared.global [%0], [%1], 16;" :: "r"(s), "l"(g));
}
__device__ __forceinline__ void cpcommit(){ asm volatile("cp.async.commit_group;"); }
__device__ __forceinline__ void cpwait2(){ asm volatile("cp.async.wait_group 2;" ::: "memory"); }
__device__ __forceinline__ void cpwait1(){ asm volatile("cp.async.wait_group 1;" ::: "memory"); }
__device__ __forceinline__ void cpwait0(){ asm volatile("cp.async.wait_group 0;" ::: "memory"); }
__device__ __forceinline__ float sigm(float x){ return 1.f/(1.f+expf(-x)); }

// ---------------- packing ----------------
__global__ __launch_bounds__(256) void pack_x_kernel(const float* __restrict__ x){
    unsigned idx = blockIdx.x*256u + threadIdx.x;    // 33,554,432
    int kl=idx&31, row=(idx>>5)&63, kc=(idx>>11)&7, rt=(idx>>14)&3, t=idx>>16;
    float v = x[((size_t)t*256 + rt*64 + row)*256 + kc*32 + kl];
    __nv_bfloat16 h = __float2bfloat16(v);
    d_xbf[idx] = *(unsigned short*)&h;
}
__global__ __launch_bounds__(256) void pack_h0_kernel(const float* __restrict__ hidden){
    unsigned idx = blockIdx.x*256u + threadIdx.x;    // 131072
    int kl=idx&31, row=(idx>>5)&63, kc8=(idx>>11)&15, rt=idx>>15;
    float v = hidden[(size_t)(rt*64+row)*512 + kc8*32 + kl];
    __nv_bfloat16 h = __float2bfloat16(v);
    d_hbf[((size_t)(0*4+rt)*16 + kc8)*2048 + row*32 + kl] = *(unsigned short*)&h;
    d_h[0][(size_t)(rt*64+row)*512 + kc8*32 + kl] = v;
}
__global__ __launch_bounds__(256) void pack_w_kernel(const float* __restrict__ w_ih,
                                                     const float* __restrict__ w_hh){
    unsigned idx = blockIdx.x*256u + threadIdx.x;    // 1,179,648
    int kl = idx&31, j = (idx>>5)&15;
    int g = idx>>9;
    int p = g%3, kc = (g/3)%24, ct = g/72;
    int kg = kc*32 + kl;
    float w;
    if (p == 0){ int r = ct*16+j;        w = (kg<256)? w_ih[r*256+kg] : w_hh[r*512+kg-256]; }
    else if(p==1){ int r = 512+ct*16+j;  w = (kg<256)? w_ih[r*256+kg] : w_hh[r*512+kg-256]; }
    else { int r = 1024+ct*16+j;
           w = (kc<8)? w_ih[r*256+kg] : w_hh[r*512+kg-256]; }
    __nv_bfloat16 h = __float2bfloat16(w);
    __nv_bfloat16 l = __float2bfloat16(w - __bfloat162float(h));
    size_t base = (size_t)(ct*24+kc)*3072 + (p*2)*512 + j*32 + kl;
    d_wbf[base]       = *(unsigned short*)&h;
    d_wbf[base + 512] = *(unsigned short*)&l;
}

// ---------------- persistent HMMA GRU (weights resident in smem) ----------------
__device__ __forceinline__ void grid_barrier(unsigned gen){
    __threadfence();
    __syncthreads();
    if(threadIdx.x==0){
        unsigned prev = atomicAdd(&g_arrive, 1u);
        if(prev == NB-1){ g_arrive = 0; __threadfence(); g_release = gen; }
        else { while(g_release < gen) {} __threadfence(); }
    }
    __syncthreads();
}

__device__ __forceinline__ void issue_chunk(int t,int par,int rt,int kc,int stage,
                                            unsigned sAb,int tid){
    const unsigned short* s0 = (kc<8)
        ? d_xbf + ((size_t)(t*4+rt)*8+kc)*2048
        : d_hbf + ((size_t)(par*4+rt)*16+(kc-8))*2048;
    unsigned db = sAb + (unsigned)stage*SA_STAGE;
#pragma unroll
    for(int i=0;i<2;i++){
        int id = tid + (i<<7);          // 0..255
        int row = id>>2, q = id&3;
        cpasync16(db + 2u*(unsigned)(row*40 + q*8), s0 + row*32 + q*8);
    }
}

__global__ __launch_bounds__(128,1) void gru_hmma(){
    extern __shared__ __align__(16) unsigned short sm[];
    const int tid = threadIdx.x, lane = tid&31, w = tid>>5;
    const int bid = blockIdx.x, rt = bid>>5, ct = bid&31;
    const unsigned sWb = smem_u32(sm);
    const unsigned sAb = sWb + SW_BYTES;
    const int sub = lane>>3;
    const unsigned laneoff = 2u*(unsigned)((((lane&7)+((sub&1)<<3))*40) + ((sub>>1)<<3));

    // ---- one-time weight preload into smem (147KB -> padded tiles) ----
    {
        const unsigned short* wsrc = d_wbf + (size_t)ct*24*3072;
        for(int i=tid; i<9216; i+=128){           // 16B units
            int tile = i>>6, r2 = i&63, j = r2>>2, q = r2&3;
            cpasync16(sWb + (unsigned)(tile*1280) + 2u*(unsigned)(j*40+q*8),
                      wsrc + tile*512 + j*32 + q*8);
        }
        cpcommit(); cpwait0(); __syncthreads();
    }

    // prologue: chunks 0..2 of step 0
    issue_chunk(0,0,rt,0,0,sAb,tid); cpcommit();
    issue_chunk(0,0,rt,1,1,sAb,tid); cpcommit();
    issue_chunk(0,0,rt,2,2,sAb,tid); cpcommit();

    for(int t=0; t<S_LEN; ++t){
        const int par = t&1;
        float accR[8], accZ[8], accI[8], accH[8];
#pragma unroll
        for(int i=0;i<8;i++){ accR[i]=0.f; accZ[i]=0.f; accI[i]=0.f; accH[i]=0.f; }

        for(int kc=0; kc<24; ++kc){
            if(kc<22) cpwait2(); else if(kc==22) cpwait1(); else cpwait0();
            __syncthreads();
            if(kc<21){ issue_chunk(t,par,rt,kc+3,(kc+3)&3,sAb,tid); cpcommit(); }

            const int stage = kc&3;
            unsigned aAddr = sAb + (unsigned)stage*SA_STAGE + (unsigned)(w*1280) + laneoff;
            float* accN = (kc<8)? accI : accH;
#pragma unroll
            for(int ks=0; ks<2; ks++){
                unsigned ko = (unsigned)(ks*32);
                unsigned ah[4];
                ldsm4(ah, aAddr + ko);
#pragma unroll
                for(int p=0;p<3;p++){
                    unsigned bh[4], bl[4];
                    unsigned tb = sWb + (unsigned)((kc*6 + p*2)*1280);
                    ldsm4(bh, tb + laneoff + ko);
                    ldsm4(bl, tb + 1280u + laneoff + ko);
                    float* acc = (p==0)? accR : (p==1)? accZ : accN;
                    mma16816(acc,   ah, bh[0], bh[2]);
                    mma16816(acc,   ah, bl[0], bl[2]);
                    mma16816(acc+4, ah, bh[1], bh[3]);
                    mma16816(acc+4, ah, bl[1], bl[3]);
                }
            }
        }

        // ---- fused gate epilogue (frag mapping verified in R11) ----
        const float* hprevB = d_h[par];
        float* houtB = d_h[par^1];
        const int rbase = rt*64 + w*16 + (lane>>2);
        const int cb = ct*16 + 2*(lane&3);
        const int klb = (ct&1)*16 + 2*(lane&3);
        const size_t imgB = (((size_t)(par^1)*4 + rt)*16 + (ct>>1))*2048;
#pragma unroll
        for(int nb=0; nb<2; nb++)
#pragma unroll
        for(int rh=0; rh<2; rh++){
            int f = nb*4 + rh*2;
            int grow = rbase + rh*8;
            int gcol = cb + nb*8;
            float2 hp = *(const float2*)&hprevB[(size_t)grow*512 + gcol];
            float r0 = sigm(accR[f]),   r1 = sigm(accR[f+1]);
            float z0 = sigm(accZ[f]),   z1 = sigm(accZ[f+1]);
            float n0 = tanhf(accI[f]   + r0*accH[f]);
            float n1 = tanhf(accI[f+1] + r1*accH[f+1]);
            float h0 = (1.f-z0)*n0 + z0*hp.x;
            float h1 = (1.f-z1)*n1 + z1*hp.y;
            *(float2*)&houtB[(size_t)grow*512 + gcol] = make_float2(h0,h1);
            __nv_bfloat16 bh0=__float2bfloat16(h0), bh1=__float2bfloat16(h1);
            int rowl = w*16 + (lane>>2) + rh*8;
            *(unsigned*)&d_hbf[imgB + (size_t)rowl*32 + klb + nb*8] =
                (unsigned)*(unsigned short*)&bh0 | ((unsigned)*(unsigned short*)&bh1 << 16);
        }

        // pre-issue next step's x chunks (0..2) — independent of h
        if(t+1 < S_LEN){
            issue_chunk(t+1,par^1,rt,0,0,sAb,tid); cpcommit();
            issue_chunk(t+1,par^1,rt,1,1,sAb,tid); cpcommit();
            issue_chunk(t+1,par^1,rt,2,2,sAb,tid); cpcommit();
        }
        grid_barrier((unsigned)(t+1));
    }
}

// ---------------- tail: generic tiled GEMM ----------------
template <int TRANSB>
__global__ __launch_bounds__(128) void gemm_tile_kernel(
        const float* __restrict__ A, int lda, const float* __restrict__ Bm, int ldb,
        float* __restrict__ C, int ldc, int K, int colTiles){
    int bid=blockIdx.x, rt=bid/colTiles, ct=bid%colTiles;
    int row0=rt*32, col0=ct*64;
    __shared__ __align__(16) float sA[16][36];
    __shared__ __align__(16) float sB[16][68];
    int tid=threadIdx.x, tr=tid>>4, tc=tid&15;
    float acc[4][4];
#pragma unroll
    for(int i=0;i<4;i++)
#pragma unroll
        for(int j=0;j<4;j++) acc[i][j]=0.f;
    for(int kk0=0;kk0<K;kk0+=16){
#pragma unroll
        for(int it=0;it<4;it++){ int idx=tid+it*128; int k=idx&15, r=idx>>4;
            sA[k][r]=A[(size_t)(row0+r)*lda+kk0+k]; }
        if(TRANSB){
#pragma unroll
            for(int it=0;it<8;it++){ int idx=tid+it*128; int k=idx&15, j=idx>>4;
                sB[k][j]=Bm[(size_t)(col0+j)*ldb+kk0+k]; }
        } else {
#pragma unroll
            for(int it=0;it<8;it++){ int idx=tid+it*128; int j=idx&63, k=idx>>6;
                sB[k][j]=Bm[(size_t)(kk0+k)*ldb+col0+j]; }
        }
        __syncthreads();
#pragma unroll
        for(int k=0;k<16;k++){
            float4 av=*(const float4*)&sA[k][tr<<2];
            float4 bv=*(const float4*)&sB[k][tc<<2];
            float a[4]={av.x,av.y,av.z,av.w}, b[4]={bv.x,bv.y,bv.z,bv.w};
#pragma unroll
            for(int i=0;i<4;i++)
#pragma unroll
                for(int j=0;j<4;j++) acc[i][j]+=a[i]*b[j];
        }
        __syncthreads();
    }
#pragma unroll
    for(int i=0;i<4;i++){
        float4 v=make_float4(acc[i][0],acc[i][1],acc[i][2],acc[i][3]);
        *(float4*)&C[(size_t)(row0+(tr<<2)+i)*ldc+col0+(tc<<2)]=v;
    }
}

__global__ __launch_bounds__(256) void softmax_kernel(){
    int b=blockIdx.x;
    const float* L=d_g+(size_t)b*HIST; float* A=d_alpha+(size_t)b*HIST;
    __shared__ float red[256];
    int tid=threadIdx.x;
    float m=-1e30f;
    for(int j=tid;j<HIST;j+=256) m=fmaxf(m,L[j]);
    red[tid]=m; __syncthreads();
    for(int s=128;s>0;s>>=1){ if(tid<s) red[tid]=fmaxf(red[tid],red[tid+s]); __syncthreads(); }
    m=red[0]; __syncthreads();
    float sum=0.f;
    for(int j=tid;j<HIST;j+=256){ float e=expf(L[j]-m); A[j]=e; sum+=e; }
    red[tid]=sum; __syncthreads();
    for(int s=128;s>0;s>>=1){ if(tid<s) red[tid]+=red[tid+s]; __syncthreads(); }
    float inv=1.f/red[0];
    for(int j=tid;j<HIST;j+=256) A[j]*=inv;
}
__global__ __launch_bounds__(256) void sigma_kernel(){
    int b=blockIdx.x, d=threadIdx.x;
    float t=d_sig[(size_t)b*DIN+d];
    d_inv_sigma[(size_t)b*DIN+d]=expf(-t);
    __shared__ float red[256];
    red[d]=t; __syncthreads();
    for(int s=128;s>0;s>>=1){ if(d<s) red[d]+=red[d+s]; __syncthreads(); }
    if(d==0) d_logdet[b]=red[0];
}
__global__ __launch_bounds__(256) void logprob_kernel(
        const float* __restrict__ x, float* __restrict__ out){
    int w=(blockIdx.x<<3)+(threadIdx.x>>5);
    int lane=threadIdx.x&31, b=w&255;
    const float4* xr=(const float4*)(x+((size_t)w<<8));
    const float4* mu=(const float4*)(d_mu+((size_t)b<<8));
    const float4* iv=(const float4*)(d_inv_sigma+((size_t)b<<8));
    float acc=0.f;
#pragma unroll
    for(int c=0;c<2;c++){
        int idx=lane+(c<<5);
        float4 xv=xr[idx], mv=mu[idx], sv=iv[idx];
        float d0=(xv.x-mv.x)*sv.x, d1=(xv.y-mv.y)*sv.y;
        float d2=(xv.z-mv.z)*sv.z, d3=(xv.w-mv.w)*sv.w;
        acc+=d0*d0+d1*d1+d2*d2+d3*d3;
    }
#pragma unroll
    for(int o=16;o;o>>=1) acc+=__shfl_xor_sync(0xffffffffu,acc,o);
    if(lane==0){
        const float log2pi=1.8378770664093453f;
        out[w]=-0.5f*(acc+256.0f*log2pi)-d_logdet[b];
    }
}

// ---------------- launch ----------------
extern "C" void kernel_launch(void* const* d_in, const int* in_sizes, int n_in,
                              void* d_out, int out_size){
    const float* x        = (const float*)d_in[0];
    const float* hidden   = (const float*)d_in[1];
    const float* external = (const float*)d_in[2];
    const float* w_ih     = (const float*)d_in[3];
    const float* w_hh     = (const float*)d_in[4];
    const float* w_alpha  = (const float*)d_in[5];
    const float* w_sigma  = (const float*)d_in[6];
    float* out = (float*)d_out;

    float *pH0, *pG, *pSig, *pAlpha, *pMu;
    cudaGetSymbolAddress((void**)&pH0, d_h);
    cudaGetSymbolAddress((void**)&pG, d_g);
    cudaGetSymbolAddress((void**)&pSig, d_sig);
    cudaGetSymbolAddress((void**)&pAlpha, d_alpha);
    cudaGetSymbolAddress((void**)&pMu, d_mu);

    cudaFuncSetAttribute(gru_hmma, cudaFuncAttributeMaxDynamicSharedMemorySize, SMEM_DYN);

    reset_barrier_kernel<<<1,1>>>();
    pack_x_kernel<<<131072,256>>>(x);
    pack_w_kernel<<<4608,256>>>(w_ih, w_hh);
    pack_h0_kernel<<<512,256>>>(hidden);

    gru_hmma<<<NB,128,SMEM_DYN>>>();        // final h lands in d_h[0]

    gemm_tile_kernel<1><<<8*32,128>>>(pH0, HID, w_alpha, HID, pG, HIST, HID, 32);
    softmax_kernel<<<BATCH,256>>>();
    gemm_tile_kernel<1><<<8*4,128>>>(pH0, HID, w_sigma, HID, pSig, DIN, HID, 4);
    sigma_kernel<<<BATCH,256>>>();
    gemm_tile_kernel<0><<<8*4,128>>>(pAlpha, HIST, external, DIN, pMu, DIN, HIST, 4);
    logprob_kernel<<<(S_LEN*BATCH)/8,256>>>(x, out);
}